// round 6
// baseline (speedup 1.0000x reference)
#include <cuda_runtime.h>

#define BB 2048
#define TT 512
#define II 64

// Scratch, layout [t][gf][b] as float4: slot (t*3+gf)*BB + b holds
// (xr_gf, xz_gf, xn_gf, 0). Padded by 8 timesteps; pad region is NEVER
// written, so it stays zero (device globals are zero-initialized) --
// odd (layer-1) lanes read it to get exact 0.0 input-side terms.
__device__ float4 g_xw4[(size_t)(TT + 8) * 3 * BB];
#define PAD_IDX ((size_t)TT * 3 * BB)

__device__ __forceinline__ float sigm(float x) {
    return __fdividef(1.0f, 1.0f + __expf(-x));
}
__device__ __forceinline__ float tanh_fast(float x) {
    float xc = fmaxf(x, -20.0f);
    float e = __expf(-2.0f * xc);
    return __fdividef(1.0f - e, 1.0f + e);
}

// ---------------------------------------------------------------------------
// Phase A (r3 form): one thread per (b,t); lanes consecutive in b so the
// three float4 scratch stores are perfectly coalesced.
// ---------------------------------------------------------------------------
__global__ void __launch_bounds__(256) phaseA(
    const float* __restrict__ x,
    const float* __restrict__ W_ih0,
    const float* __restrict__ b_ih0)
{
    __shared__ float4 Ws4[9 * 16];
    __shared__ float bs[9];
    if (threadIdx.x < 144) Ws4[threadIdx.x] = ((const float4*)W_ih0)[threadIdx.x];
    if (threadIdx.x < 9)   bs[threadIdx.x] = b_ih0[threadIdx.x];
    __syncthreads();

    int idx = blockIdx.x * blockDim.x + threadIdx.x;   // 0 .. B*T-1
    int b = idx & (BB - 1);
    int t = idx >> 11;

    const float4* xp = reinterpret_cast<const float4*>(x + ((size_t)b * TT + t) * II);

    float acc[9];
#pragma unroll
    for (int g = 0; g < 9; g++) acc[g] = bs[g];

#pragma unroll
    for (int i = 0; i < II / 4; i++) {
        float4 xv = xp[i];
#pragma unroll
        for (int g = 0; g < 9; g++) {
            float4 wv = Ws4[g * 16 + i];
            acc[g] = fmaf(xv.w, wv.w, fmaf(xv.z, wv.z,
                     fmaf(xv.y, wv.y, fmaf(xv.x, wv.x, acc[g]))));
        }
    }

    float4* o = g_xw4 + (size_t)t * 3 * BB + b;
    o[0]        = make_float4(acc[0], acc[3], acc[6], 0.f);
    o[BB]       = make_float4(acc[1], acc[4], acc[7], 0.f);
    o[2 * BB]   = make_float4(acc[2], acc[5], acc[8], 0.f);
}

// ---------------------------------------------------------------------------
// Phase B: 2 lanes per element (even = layer 0, odd = layer 1 one step
// behind, h0 passed via shfl). Block = 256 threads -> 8 warps -> 2 warps per
// SMSP so dependency stalls of one warp are covered by the other.
// Branch-free loop body, no SELs (zero-weight / zero-pad trick), true
// 4-deep register ring for the scratch prefetch.
// ---------------------------------------------------------------------------
__global__ void __launch_bounds__(256, 1) gru_rec(
    const float* __restrict__ W_hh0, const float* __restrict__ b_hh0,
    const float* __restrict__ W_ih1, const float* __restrict__ b_ih1,
    const float* __restrict__ W_hh1, const float* __restrict__ b_hh1,
    float* __restrict__ out)
{
    const int tid    = blockIdx.x * blockDim.x + threadIdx.x;
    const int lane   = threadIdx.x & 31;
    const int parity = lane & 1;                  // 0: layer0, 1: layer1
    const int e      = tid >> 1;                  // batch element
    const int src    = lane & ~1;                 // partner (layer-0) lane

    // Own-layer recurrent weights. Input-side weights are zeroed on even
    // lanes so their ih[] is exactly 0.0 (b4 carries the real xw terms).
    const float* whh_p = parity ? W_hh1 : W_hh0;
    const float* bhh_p = parity ? b_hh1 : b_hh0;
    float wh[9][3], bh[9], wi[9][3], bi[9];
#pragma unroll
    for (int r = 0; r < 9; r++) {
        bh[r] = __ldg(bhh_p + r);
        bi[r] = parity ? __ldg(b_ih1 + r) : 0.f;
#pragma unroll
        for (int k = 0; k < 3; k++) {
            wh[r][k] = __ldg(whh_p + r * 3 + k);
            wi[r][k] = parity ? __ldg(W_ih1 + r * 3 + k) : 0.f;
        }
    }

    float h[3] = {0.f, 0.f, 0.f};

    // Even lanes walk the real scratch; odd lanes sit on the zero pad with
    // stride 0 (always read exact 0.0 -> their b4 contribution vanishes).
    const float4* xb  = g_xw4 + (parity ? PAD_IDX : (size_t)e);
    const size_t  xstr = parity ? 0 : (size_t)BB;

    float4 buf[4][3];
#pragma unroll
    for (int s = 0; s < 4; s++)
#pragma unroll
        for (int gf = 0; gf < 3; gf++)
            buf[s][gf] = xb[(size_t)(s * 3 + gf) * xstr];

    // One fused step: shfl h0, both matvecs, gates. hn returned, h untouched.
    auto step = [&](const float4 b4[3], float hn[3]) {
        float ho[3];
#pragma unroll
        for (int k = 0; k < 3; k++)
            ho[k] = __shfl_sync(0xffffffffu, h[k], src);
        float gh[9], ih[9];
#pragma unroll
        for (int r = 0; r < 9; r++) {
            gh[r] = fmaf(wh[r][2], h[2],  fmaf(wh[r][1], h[1],  fmaf(wh[r][0], h[0],  bh[r])));
            ih[r] = fmaf(wi[r][2], ho[2], fmaf(wi[r][1], ho[1], fmaf(wi[r][0], ho[0], bi[r])));
        }
#pragma unroll
        for (int j = 0; j < 3; j++) {
            float xr = b4[j].x + ih[j];        // even: b4 real, ih==0
            float xz = b4[j].y + ih[3 + j];    // odd:  b4==0,  ih real
            float xn = b4[j].z + ih[6 + j];
            float r  = sigm(xr + gh[j]);
            float z  = sigm(xz + gh[3 + j]);
            float n  = tanh_fast(fmaf(r, gh[6 + j], xn));
            hn[j] = fmaf(z, h[j] - n, n);
        }
    };

    // Peel t=0: even lanes commit h0^0; odd lanes stay 0.
    {
        float hn[3];
        step(buf[0], hn);
#pragma unroll
        for (int j = 0; j < 3; j++) h[j] = parity ? 0.f : hn[j];
#pragma unroll
        for (int gf = 0; gf < 3; gf++)
            buf[0][gf] = xb[(size_t)(4 * 3 + gf) * xstr];
    }

    // Main loop t=1..511: even lanes -> h0^t, odd lanes -> h1^{t-1}.
#pragma unroll 4
    for (int t = 1; t < TT; t++) {
        float hn[3];
        step(buf[t & 3], hn);
#pragma unroll
        for (int j = 0; j < 3; j++) h[j] = hn[j];
#pragma unroll
        for (int gf = 0; gf < 3; gf++)
            buf[t & 3][gf] = xb[(size_t)((t + 4) * 3 + gf) * xstr];
    }

    // Epilogue: final layer-1 step consumes h0^{511}.
    {
        float hn[3];
        step(buf[0], hn);
#pragma unroll
        for (int j = 0; j < 3; j++) h[j] = parity ? hn[j] : h[j];
    }

    if (parity) {
        out[e * 3 + 0] = h[0];
        out[e * 3 + 1] = h[1];
        out[e * 3 + 2] = h[2];
    }
}

extern "C" void kernel_launch(void* const* d_in, const int* in_sizes, int n_in,
                              void* d_out, int out_size)
{
    const float* x     = (const float*)d_in[0];
    const float* W_ih0 = (const float*)d_in[1];
    const float* W_hh0 = (const float*)d_in[2];
    const float* b_ih0 = (const float*)d_in[3];
    const float* b_hh0 = (const float*)d_in[4];
    const float* W_ih1 = (const float*)d_in[5];
    const float* W_hh1 = (const float*)d_in[6];
    const float* b_ih1 = (const float*)d_in[7];
    const float* b_hh1 = (const float*)d_in[8];
    float* out = (float*)d_out;

    phaseA<<<(BB * TT) / 256, 256>>>(x, W_ih0, b_ih0);
    // 4096 threads total -> 16 blocks x 256: 8 warps/SM, 2 per SMSP.
    gru_rec<<<16, 256>>>(W_hh0, b_hh0, W_ih1, b_ih1, W_hh1, b_hh1, out);
}